// round 8
// baseline (speedup 1.0000x reference)
#include <cuda_runtime.h>

#define TPB 128
#define W   1116

__device__ __forceinline__ float softf(float c, float t) {
    return copysignf(fmaxf(fabsf(c) - t, 0.0f), c);
}

// Shared layout (floats), all bases 16B-aligned:
//  [0..571]      eA (front pad 4 -> data at 4)      \  forward set A
//  [572..1143]   oA (front pad 4 -> data at 576)    /
//  [1144..1439]  eB (front pad 4 -> data at 1148)   \  forward set B
//  [1440..1735]  oB (front pad 4 -> data at 1444)   /
//  [1736..1755]  a7 (final approx, linear, 15 used + pad)
//  [1756..2915]  sD (all detail levels, 4-aligned regions)
//  Inverse aliases: lin0 = sm+0 (<=1120), lin1 = sm+1120 (<=616 slack to a7)
__global__ void __launch_bounds__(TPB, 8) wavelet_kernel(
    const float* __restrict__ x, const float* __restrict__ rawthr,
    float* __restrict__ out)
{
    constexpr float DLO[8] = {
        -0.010597401784997278f,  0.032883011666982945f,
         0.030841381835986965f, -0.18703481171888114f,
        -0.02798376941698385f,   0.6308807679295904f,
         0.7148465705525415f,    0.23037781330885523f };

    constexpr int NS[8]   = {1116, 561, 284, 145, 76, 41, 24, 15};
    constexpr int DOFF[7] = {0, 564, 848, 996, 1072, 1116, 1140};

    __shared__ __align__(16) float sm[2916];
    float* const EP[2] = { sm + 4,   sm + 1148 };
    float* const OP[2] = { sm + 576, sm + 1444 };
    float* const a7 = sm + 1736;
    float* const sD = sm + 1756;

    const int tid = threadIdx.x;
    const long row = blockIdx.x;
    const float thr = fmaxf(rawthr[0], 0.01f);

    // ---- Stage input row, de-interleaved into e/o arrays ----
    {
        const float4* xin = (const float4*)(x + row * W);
        float* e = EP[0]; float* o = OP[0];
        for (int i = tid; i < W / 4; i += TPB) {
            float4 v = xin[i];
            ((float2*)e)[i] = make_float2(v.x, v.z);
            ((float2*)o)[i] = make_float2(v.y, v.w);
        }
        if (tid < 4) { sm[tid] = 0.f; sm[572 + tid] = 0.f; sm[1144 + tid] = 0.f; sm[1440 + tid] = 0.f; }
        if (tid < 8) { e[558 + tid] = 0.f; o[558 + tid] = 0.f; }
    }
    __syncthreads();

    // ---- Forward: 7 DWT levels, 8 outputs/thread ----
    #pragma unroll
    for (int l = 0; l < 7; l++) {
        const int nout = NS[l + 1];
        const float* se = EP[l & 1];
        const float* so = OP[l & 1];
        float* de  = EP[(l + 1) & 1];
        float* do_ = OP[(l + 1) & 1];
        float* dd  = sD + DOFF[l];
        const int g8 = (nout + 7) >> 3;

        for (int t = tid; t < g8; t += TPB) {
            const float* ep = se + 8 * t - 4;   // 16B aligned
            const float* op = so + 8 * t - 4;
            float4 E0 = *(const float4*)(ep);
            float4 E1 = *(const float4*)(ep + 4);
            float4 E2 = *(const float4*)(ep + 8);
            float4 O0 = *(const float4*)(op);
            float4 O1 = *(const float4*)(op + 4);
            float4 O2 = *(const float4*)(op + 8);
            float we[12] = {E0.x,E0.y,E0.z,E0.w, E1.x,E1.y,E1.z,E1.w, E2.x,E2.y,E2.z,E2.w};
            float wo[12] = {O0.x,O0.y,O0.z,O0.w, O1.x,O1.y,O1.z,O1.w, O2.x,O2.y,O2.z,O2.w};

            float ca[8], cd[8];
            #pragma unroll
            for (int k = 0; k < 8; k++) {
                float a = 0.f, d = 0.f;
                #pragma unroll
                for (int m = 0; m < 4; m++) {
                    float ev = we[k + 4 - m], ov = wo[k + 4 - m];
                    a = fmaf(DLO[2 * m + 1],  ev, a);   // dec_lo odd taps -> even samples
                    a = fmaf(DLO[2 * m],      ov, a);   // dec_lo even taps -> odd samples
                    d = fmaf(DLO[6 - 2 * m],  ev, d);   // dec_hi odd taps
                    d = fmaf(-DLO[7 - 2 * m], ov, d);   // dec_hi even taps
                }
                ca[k] = a;
                cd[k] = softf(d, thr);
            }

            if (8 * t + 7 < nout) {  // full group: all-vector stores
                *(float4*)(dd + 8 * t)     = make_float4(cd[0], cd[1], cd[2], cd[3]);
                *(float4*)(dd + 8 * t + 4) = make_float4(cd[4], cd[5], cd[6], cd[7]);
                if (l < 6) {
                    *(float4*)(de  + 4 * t) = make_float4(ca[0], ca[2], ca[4], ca[6]);
                    *(float4*)(do_ + 4 * t) = make_float4(ca[1], ca[3], ca[5], ca[7]);
                } else {
                    *(float4*)(a7 + 8 * t)     = make_float4(
                        softf(ca[0], thr), softf(ca[1], thr), softf(ca[2], thr), softf(ca[3], thr));
                    *(float4*)(a7 + 8 * t + 4) = make_float4(
                        softf(ca[4], thr), softf(ca[5], thr), softf(ca[6], thr), softf(ca[7], thr));
                }
            } else {                 // guarded tail group
                #pragma unroll
                for (int k = 0; k < 8; k++) {
                    int i = 8 * t + k;
                    if (i < nout) {
                        dd[i] = cd[k];
                        if (l < 6) {
                            if (i & 1) do_[i >> 1] = ca[k];
                            else       de[i >> 1]  = ca[k];
                        } else {
                            a7[i] = softf(ca[k], thr);
                        }
                    }
                }
            }
        }
        // zero tail pads of destination arrays for next level's windows
        if (l < 6 && tid < 8) {
            const int ec = (nout + 1) >> 1, oc = nout >> 1;
            de[ec + tid]  = 0.f;
            do_[oc + tid] = 0.f;
        }
        __syncthreads();
    }

    // ---- Inverse: levels s=6..1 in smem, 4 pairs/thread ----
    float* const lin0 = sm;
    float* const lin1 = sm + 1120;

    #pragma unroll
    for (int s = 6; s >= 1; s--) {
        const int n = NS[s + 1];                     // detail length (truncation implicit)
        const float* a = (s == 6) ? a7 : ((((5 - s) & 1)) ? lin1 : lin0);
        float* dst     = (((6 - s) & 1)) ? lin1 : lin0;
        const float* d = sD + DOFF[s];
        const int pairs = n - 3;
        const int g4 = (pairs + 3) >> 2;

        for (int t = tid; t < g4; t += TPB) {
            if (4 * t + 3 < pairs) {  // full group
                float4 A0 = *(const float4*)(a + 4 * t);
                float4 A1 = *(const float4*)(a + 4 * t + 4);
                float4 D0 = *(const float4*)(d + 4 * t);
                float4 D1 = *(const float4*)(d + 4 * t + 4);
                float wa[8] = {A0.x,A0.y,A0.z,A0.w, A1.x,A1.y,A1.z,A1.w};
                float wd[8] = {D0.x,D0.y,D0.z,D0.w, D1.x,D1.y,D1.z,D1.w};

                float y[8];
                #pragma unroll
                for (int r = 0; r < 4; r++) {
                    float ye = 0.f, yo = 0.f;
                    #pragma unroll
                    for (int q = 0; q < 4; q++) {
                        float av = wa[r + 3 - q], dv = wd[r + 3 - q];
                        ye = fmaf(DLO[7 - 2 * q],  av, ye);
                        ye = fmaf(DLO[2 * q],      dv, ye);
                        yo = fmaf(DLO[6 - 2 * q],  av, yo);
                        yo = fmaf(-DLO[2 * q + 1], dv, yo);
                    }
                    y[2 * r] = ye; y[2 * r + 1] = yo;
                }
                *(float4*)(dst + 8 * t)     = make_float4(y[0], y[1], y[2], y[3]);
                *(float4*)(dst + 8 * t + 4) = make_float4(y[4], y[5], y[6], y[7]);
            } else {                  // guarded tail: scalar per pair
                #pragma unroll
                for (int r = 0; r < 4; r++) {
                    int p = 4 * t + r;
                    if (p < pairs) {
                        float ye = 0.f, yo = 0.f;
                        #pragma unroll
                        for (int q = 0; q < 4; q++) {
                            float av = a[p + 3 - q], dv = d[p + 3 - q];
                            ye = fmaf(DLO[7 - 2 * q],  av, ye);
                            ye = fmaf(DLO[2 * q],      dv, ye);
                            yo = fmaf(DLO[6 - 2 * q],  av, yo);
                            yo = fmaf(-DLO[2 * q + 1], dv, yo);
                        }
                        *(float2*)(dst + 2 * p) = make_float2(ye, yo);
                    }
                }
            }
        }
        __syncthreads();
    }

    // ---- Inverse s=0: straight to global (pairs = 558 -> exactly 1116 floats) ----
    {
        const float* a = lin1;          // result of s=1 (length 562, use 561)
        const float* d = sD;            // DOFF[0] = 0, length 561
        float* orow = out + row * W;
        const int pairs = 558;
        const int g4 = 140;

        for (int t = tid; t < g4; t += TPB) {
            if (4 * t + 3 < pairs) {
                float4 A0 = *(const float4*)(a + 4 * t);
                float4 A1 = *(const float4*)(a + 4 * t + 4);
                float4 D0 = *(const float4*)(d + 4 * t);
                float4 D1 = *(const float4*)(d + 4 * t + 4);
                float wa[8] = {A0.x,A0.y,A0.z,A0.w, A1.x,A1.y,A1.z,A1.w};
                float wd[8] = {D0.x,D0.y,D0.z,D0.w, D1.x,D1.y,D1.z,D1.w};

                float y[8];
                #pragma unroll
                for (int r = 0; r < 4; r++) {
                    float ye = 0.f, yo = 0.f;
                    #pragma unroll
                    for (int q = 0; q < 4; q++) {
                        float av = wa[r + 3 - q], dv = wd[r + 3 - q];
                        ye = fmaf(DLO[7 - 2 * q],  av, ye);
                        ye = fmaf(DLO[2 * q],      dv, ye);
                        yo = fmaf(DLO[6 - 2 * q],  av, yo);
                        yo = fmaf(-DLO[2 * q + 1], dv, yo);
                    }
                    y[2 * r] = ye; y[2 * r + 1] = yo;
                }
                *(float4*)(orow + 8 * t)     = make_float4(y[0], y[1], y[2], y[3]);
                *(float4*)(orow + 8 * t + 4) = make_float4(y[4], y[5], y[6], y[7]);
            } else {   // tail: pairs 556,557 -> outputs 1112..1115
                #pragma unroll
                for (int r = 0; r < 4; r++) {
                    int p = 4 * t + r;
                    if (p < pairs) {
                        float ye = 0.f, yo = 0.f;
                        #pragma unroll
                        for (int q = 0; q < 4; q++) {
                            float av = a[p + 3 - q], dv = d[p + 3 - q];
                            ye = fmaf(DLO[7 - 2 * q],  av, ye);
                            ye = fmaf(DLO[2 * q],      dv, ye);
                            yo = fmaf(DLO[6 - 2 * q],  av, yo);
                            yo = fmaf(-DLO[2 * q + 1], dv, yo);
                        }
                        *(float2*)(orow + 2 * p) = make_float2(ye, yo);
                    }
                }
            }
        }
    }
}

extern "C" void kernel_launch(void* const* d_in, const int* in_sizes, int n_in,
                              void* d_out, int out_size) {
    const float* x   = (const float*)d_in[0];
    const float* thr = (const float*)d_in[1];
    float* out = (float*)d_out;
    const int rows = in_sizes[0] / W;
    wavelet_kernel<<<rows, TPB>>>(x, thr, out);
}

// round 10
// speedup vs baseline: 1.4731x; 1.4731x over previous
#include <cuda_runtime.h>

#define TPB 128
#define W   1116

__device__ __forceinline__ float softf(float c, float t) {
    return copysignf(fmaxf(fabsf(c) - t, 0.0f), c);
}

// Shared layout (floats), all bases 16B-aligned:
//  [0..571]      eA (front pad 4 -> data at 4)      \  forward set A
//  [572..1143]   oA (front pad 4 -> data at 576)    /
//  [1144..1439]  eB (front pad 4 -> data at 1148)   \  forward set B
//  [1440..1735]  oB (front pad 4 -> data at 1444)   /
//  [1736..1755]  a7 (final approx, linear, 15 used)
//  [1756..2915]  sD (all detail levels, 4-aligned regions)
//  Inverse aliases: lin0 = sm+0 (<=1120), lin1 = sm+1120 (<=616 slack to a7+sD)
__global__ void __launch_bounds__(TPB, 8) wavelet_kernel(
    const float* __restrict__ x, const float* __restrict__ rawthr,
    float* __restrict__ out)
{
    constexpr float DLO[8] = {
        -0.010597401784997278f,  0.032883011666982945f,
         0.030841381835986965f, -0.18703481171888114f,
        -0.02798376941698385f,   0.6308807679295904f,
         0.7148465705525415f,    0.23037781330885523f };

    constexpr int NS[8]   = {1116, 561, 284, 145, 76, 41, 24, 15};
    constexpr int DOFF[7] = {0, 564, 848, 996, 1072, 1116, 1140};

    __shared__ __align__(16) float sm[2916];
    float* const EP[2] = { sm + 4,   sm + 1148 };
    float* const OP[2] = { sm + 576, sm + 1444 };
    float* const a7 = sm + 1736;
    float* const sD = sm + 1756;

    const int tid = threadIdx.x;
    const long row = blockIdx.x;
    const float thr = fmaxf(rawthr[0], 0.01f);

    // ---- Stage input row, de-interleaved into e/o arrays ----
    {
        const float4* xin = (const float4*)(x + row * W);
        float* e = EP[0]; float* o = OP[0];
        for (int i = tid; i < W / 4; i += TPB) {
            float4 v = xin[i];
            ((float2*)e)[i] = make_float2(v.x, v.z);
            ((float2*)o)[i] = make_float2(v.y, v.w);
        }
        if (tid < 4) { sm[tid] = 0.f; sm[572 + tid] = 0.f; sm[1144 + tid] = 0.f; sm[1440 + tid] = 0.f; }
        if (tid < 8) { e[558 + tid] = 0.f; o[558 + tid] = 0.f; }
    }
    __syncthreads();

    // ---- Forward: 7 DWT levels, 4 outputs/thread (R5 geometry) ----
    #pragma unroll
    for (int l = 0; l < 7; l++) {
        const int nout = NS[l + 1];
        const float* se = EP[l & 1];
        const float* so = OP[l & 1];
        float* de  = EP[(l + 1) & 1];
        float* do_ = OP[(l + 1) & 1];
        float* dd  = sD + DOFF[l];
        const int groups = (nout + 3) >> 2;

        for (int g = tid; g < groups; g += TPB) {
            float4 E0 = *(const float4*)(se + 4 * g - 4);
            float4 E1 = *(const float4*)(se + 4 * g);
            float4 O0 = *(const float4*)(so + 4 * g - 4);
            float4 O1 = *(const float4*)(so + 4 * g);
            float we[8] = {E0.x, E0.y, E0.z, E0.w, E1.x, E1.y, E1.z, E1.w};
            float wo[8] = {O0.x, O0.y, O0.z, O0.w, O1.x, O1.y, O1.z, O1.w};

            float ca[4], cd[4];
            #pragma unroll
            for (int k = 0; k < 4; k++) {
                float a = 0.f, d = 0.f;
                #pragma unroll
                for (int m = 0; m < 4; m++) {
                    float ev = we[k + 4 - m], ov = wo[k + 4 - m];
                    a = fmaf(DLO[2 * m + 1],  ev, a);
                    a = fmaf(DLO[2 * m],      ov, a);
                    d = fmaf(DLO[6 - 2 * m],  ev, d);
                    d = fmaf(-DLO[7 - 2 * m], ov, d);
                }
                ca[k] = a;
                cd[k] = softf(d, thr);
            }

            if (4 * g + 3 < nout) {
                *(float4*)(dd + 4 * g) = make_float4(cd[0], cd[1], cd[2], cd[3]);
                if (l < 6) {
                    *(float2*)(de  + 2 * g) = make_float2(ca[0], ca[2]);
                    *(float2*)(do_ + 2 * g) = make_float2(ca[1], ca[3]);
                } else {
                    *(float4*)(a7 + 4 * g) = make_float4(
                        softf(ca[0], thr), softf(ca[1], thr),
                        softf(ca[2], thr), softf(ca[3], thr));
                }
            } else {
                #pragma unroll
                for (int k = 0; k < 4; k++) {
                    int i = 4 * g + k;
                    if (i < nout) {
                        dd[i] = cd[k];
                        if (l < 6) {
                            if (i & 1) do_[i >> 1] = ca[k];
                            else       de[i >> 1]  = ca[k];
                        } else {
                            a7[i] = softf(ca[k], thr);
                        }
                    }
                }
            }
        }
        if (l < 6 && tid < 8) {
            const int ec = (nout + 1) >> 1, oc = nout >> 1;
            de[ec + tid]  = 0.f;
            do_[oc + tid] = 0.f;
        }
        __syncthreads();
    }

    // ---- Inverse: levels s=6..1 in smem, 2 pairs/thread (R5 geometry) ----
    float* const lin0 = sm;
    float* const lin1 = sm + 1120;

    #pragma unroll
    for (int s = 6; s >= 1; s--) {
        const int n = NS[s + 1];
        const float* a = (s == 6) ? a7 : ((((5 - s) & 1)) ? lin1 : lin0);
        float* dst     = (((6 - s) & 1)) ? lin1 : lin0;
        const float* d = sD + DOFF[s];
        const int pairs  = n - 3;
        const int groups = (pairs + 1) >> 1;

        for (int g = tid; g < groups; g += TPB) {
            float2 A0 = *(const float2*)(a + 2 * g);
            float2 A1 = *(const float2*)(a + 2 * g + 2);
            float2 A2 = *(const float2*)(a + 2 * g + 4);
            float2 D0 = *(const float2*)(d + 2 * g);
            float2 D1 = *(const float2*)(d + 2 * g + 2);
            float2 D2 = *(const float2*)(d + 2 * g + 4);
            float wa[5] = {A0.x, A0.y, A1.x, A1.y, A2.x};
            float wd[5] = {D0.x, D0.y, D1.x, D1.y, D2.x};

            float ye0 = 0.f, yo0 = 0.f, ye1 = 0.f, yo1 = 0.f;
            #pragma unroll
            for (int q = 0; q < 4; q++) {
                ye0 = fmaf(DLO[7 - 2 * q],  wa[3 - q], ye0);
                ye0 = fmaf(DLO[2 * q],      wd[3 - q], ye0);
                yo0 = fmaf(DLO[6 - 2 * q],  wa[3 - q], yo0);
                yo0 = fmaf(-DLO[2 * q + 1], wd[3 - q], yo0);
                ye1 = fmaf(DLO[7 - 2 * q],  wa[4 - q], ye1);
                ye1 = fmaf(DLO[2 * q],      wd[4 - q], ye1);
                yo1 = fmaf(DLO[6 - 2 * q],  wa[4 - q], yo1);
                yo1 = fmaf(-DLO[2 * q + 1], wd[4 - q], yo1);
            }

            if (2 * g + 1 < pairs) {
                *(float4*)(dst + 4 * g) = make_float4(ye0, yo0, ye1, yo1);
            } else {
                *(float2*)(dst + 4 * g) = make_float2(ye0, yo0);
            }
        }
        __syncthreads();
    }

    // ---- Inverse s=0: 2 pairs/thread, straight to global.
    //      pairs = 558, groups = 279 (exactly covers 1116 outputs, no tail). ----
    {
        const float* a = lin1;          // s=1 result (length 562, use 561)
        const float* d = sD;            // DOFF[0] = 0, length 561
        float* orow = out + row * W;
        const int groups = 279;

        for (int g = tid; g < groups; g += TPB) {
            float2 A0 = *(const float2*)(a + 2 * g);
            float2 A1 = *(const float2*)(a + 2 * g + 2);
            float2 A2 = *(const float2*)(a + 2 * g + 4);
            float2 D0 = *(const float2*)(d + 2 * g);
            float2 D1 = *(const float2*)(d + 2 * g + 2);
            float2 D2 = *(const float2*)(d + 2 * g + 4);
            float wa[5] = {A0.x, A0.y, A1.x, A1.y, A2.x};
            float wd[5] = {D0.x, D0.y, D1.x, D1.y, D2.x};

            float ye0 = 0.f, yo0 = 0.f, ye1 = 0.f, yo1 = 0.f;
            #pragma unroll
            for (int q = 0; q < 4; q++) {
                ye0 = fmaf(DLO[7 - 2 * q],  wa[3 - q], ye0);
                ye0 = fmaf(DLO[2 * q],      wd[3 - q], ye0);
                yo0 = fmaf(DLO[6 - 2 * q],  wa[3 - q], yo0);
                yo0 = fmaf(-DLO[2 * q + 1], wd[3 - q], yo0);
                ye1 = fmaf(DLO[7 - 2 * q],  wa[4 - q], ye1);
                ye1 = fmaf(DLO[2 * q],      wd[4 - q], ye1);
                yo1 = fmaf(DLO[6 - 2 * q],  wa[4 - q], yo1);
                yo1 = fmaf(-DLO[2 * q + 1], wd[4 - q], yo1);
            }

            *(float4*)(orow + 4 * g) = make_float4(ye0, yo0, ye1, yo1);
        }
    }
}

extern "C" void kernel_launch(void* const* d_in, const int* in_sizes, int n_in,
                              void* d_out, int out_size) {
    const float* x   = (const float*)d_in[0];
    const float* thr = (const float*)d_in[1];
    float* out = (float*)d_out;
    const int rows = in_sizes[0] / W;
    wavelet_kernel<<<rows, TPB>>>(x, thr, out);
}